// round 8
// baseline (speedup 1.0000x reference)
#include <cuda_runtime.h>
#include <cuda_fp16.h>

#define NN 100000
#define EE 1600000
#define HH 64
#define GG 128
#define CC 10
#define NB1 98   // ceil(NN/1024)

// ---------------- scratch (device globals: no runtime allocation) ----------------
__device__ int     g_csrc[EE];
__device__ int     g_deg[NN];
__device__ int     g_rowptr[NN];
__device__ int     g_cursor[NN];
__device__ int     g_incl[NN];
__device__ int     g_bsum[128];
__device__ __half2 g_h1h[(size_t)NN * 32];   // fp16 pre-activation features (both layers)
__device__ float   g_hx[(size_t)NN * HH];    // layer-1 post softmax+bias+elu (fp32)
__device__ float   g_als[NN];
__device__ float   g_ald[NN];
__device__ int     g_i64;

__device__ __forceinline__ float lrelu(float x) { return x > 0.f ? x : 0.2f * x; }
__device__ __forceinline__ float elu_(float x)  { return x > 0.f ? x : expm1f(x); }

// ---------------- zero + dtype detect (int64 indices have zero high words) ----------
__global__ void zero_kernel(const int* __restrict__ ei_w, float* __restrict__ out) {
    int i = blockIdx.x * blockDim.x + threadIdx.x;
    if (i == 0) {
        int flag = 1;
        for (int k = 0; k < 64; k++)
            if (ei_w[2 * k + 1] != 0) flag = 0;
        g_i64 = flag;
    }
    if (i < NN) g_deg[i] = 0;
    if (i < GG * CC) out[i] = 0.f;
}

__global__ void prep_kernel(const int* __restrict__ ei_w) {
    int i = blockIdx.x * blockDim.x + threadIdx.x;
    if (i >= EE) return;
    int d;
    if (g_i64) d = (int)((const long long*)ei_w)[EE + i];
    else       d = ei_w[EE + i];
    atomicAdd(&g_deg[d], 1);
}

__global__ void scan1_kernel() {
    __shared__ int sm[1024];
    int t = threadIdx.x;
    int i = blockIdx.x * 1024 + t;
    int v = (i < NN) ? g_deg[i] : 0;
    sm[t] = v;
    __syncthreads();
#pragma unroll
    for (int off = 1; off < 1024; off <<= 1) {
        int x = (t >= off) ? sm[t - off] : 0;
        __syncthreads();
        sm[t] += x;
        __syncthreads();
    }
    if (i < NN) g_incl[i] = sm[t];
    if (t == 1023) g_bsum[blockIdx.x] = sm[t];
}

__global__ void scan2_kernel() {
    __shared__ int sm[128];
    int t = threadIdx.x;
    int v = (t < NB1) ? g_bsum[t] : 0;
    sm[t] = v;
    __syncthreads();
#pragma unroll
    for (int off = 1; off < 128; off <<= 1) {
        int x = (t >= off) ? sm[t - off] : 0;
        __syncthreads();
        sm[t] += x;
        __syncthreads();
    }
    if (t < NB1) g_bsum[t] = sm[t] - v;   // exclusive
}

__global__ void scan3_kernel() {
    int i = blockIdx.x * blockDim.x + threadIdx.x;
    if (i >= NN) return;
    int excl = g_incl[i] - g_deg[i] + g_bsum[i >> 10];
    g_rowptr[i] = excl;
    g_cursor[i] = excl;
}

__global__ void fill_kernel(const int* __restrict__ ei_w) {
    int i = blockIdx.x * blockDim.x + threadIdx.x;
    if (i >= EE) return;
    int s, d;
    if (g_i64) {
        const long long* e64 = (const long long*)ei_w;
        s = (int)e64[i];
        d = (int)e64[EE + i];
    } else {
        s = ei_w[i];
        d = ei_w[EE + i];
    }
    int slot = atomicAdd(&g_cursor[d], 1);
    g_csrc[slot] = s;
}

// ---------------- GEMM (Nx64 @ 64x64) + epilogue: fp16 h row + attention halves -----
// mode 0: read external x; mode 1: read g_hx
__global__ __launch_bounds__(128) void gemm_gat(
    int mode, const float* __restrict__ xext, const float* __restrict__ W,
    const float* __restrict__ avs, const float* __restrict__ avd)
{
    __shared__ float4 Ws[64 * 16];
    __shared__ float as_s[64], ad_s[64];
    int tid = threadIdx.x;
    const float4* W4 = (const float4*)W;
    for (int i = tid; i < 64 * 16; i += 128) Ws[i] = W4[i];
    if (tid < 64) { as_s[tid] = avs[tid]; ad_s[tid] = avd[tid]; }
    __syncthreads();

    int row = blockIdx.x * 128 + tid;
    if (row >= NN) return;
    size_t base = (size_t)row * HH;

    float o[64];
#pragma unroll
    for (int c = 0; c < 64; c++) o[c] = 0.f;

    const float* xin = mode ? g_hx : xext;
    const float4* xp = (const float4*)(xin + base);
#pragma unroll 4
    for (int k4 = 0; k4 < 16; k4++) {
        float4 v = xp[k4];
        float xk[4] = {v.x, v.y, v.z, v.w};
#pragma unroll
        for (int kk = 0; kk < 4; kk++) {
            int k = 4 * k4 + kk;
            float xv = xk[kk];
#pragma unroll
            for (int c4 = 0; c4 < 16; c4++) {
                float4 w = Ws[k * 16 + c4];
                o[4 * c4 + 0] = fmaf(xv, w.x, o[4 * c4 + 0]);
                o[4 * c4 + 1] = fmaf(xv, w.y, o[4 * c4 + 1]);
                o[4 * c4 + 2] = fmaf(xv, w.z, o[4 * c4 + 2]);
                o[4 * c4 + 3] = fmaf(xv, w.w, o[4 * c4 + 3]);
            }
        }
    }

    float als = 0.f, ald = 0.f;
    __half2 hrow[32];
#pragma unroll
    for (int c2 = 0; c2 < 32; c2++) {
        float a = o[2 * c2], b = o[2 * c2 + 1];
        hrow[c2] = __floats2half2_rn(a, b);
        als += a * as_s[2 * c2] + b * as_s[2 * c2 + 1];
        ald += a * ad_s[2 * c2] + b * ad_s[2 * c2 + 1];
    }
    float4* dst = (float4*)(g_h1h + (size_t)row * 32);
    const float4* srcv = (const float4*)hrow;
#pragma unroll
    for (int i = 0; i < 8; i++) dst[i] = srcv[i];

    g_als[row] = als;
    g_ald[row] = ald;
}

// ---------------- warp-per-dst gather core: softmax + weighted sum + bias + elu -----
// h rows are fp16 (half2 per lane); accumulation fp32. Returns this lane's 2 features.
__device__ __forceinline__ float2 gather_row(int d, int lane, const float* __restrict__ bs) {
    const __half2* __restrict__ h = g_h1h;
    const unsigned FULL = 0xffffffffu;
    float aldd = g_ald[d];
    float m_self = lrelu(g_als[d] + aldd);
    int row = g_rowptr[d];
    int deg = g_deg[d];

    float2 hv0 = __half22float2(h[(size_t)d * 32 + lane]);
    float accx, accy, den, exs;

    if (deg <= 32) {
        int   s_l = 0;
        float e_l = -1e30f;
        if (lane < deg) {
            s_l = g_csrc[row + lane];
            e_l = lrelu(g_als[s_l] + aldd);
        }
        float m = fmaxf(m_self, e_l);
#pragma unroll
        for (int off = 16; off; off >>= 1) m = fmaxf(m, __shfl_xor_sync(FULL, m, off));
        float ex_l = (lane < deg) ? __expf(e_l - m) : 0.f;
        den = ex_l;
        exs = __expf(m_self - m);
        accx = exs * hv0.x;
        accy = exs * hv0.y;
        int k = 0;
        for (; k + 4 <= deg; k += 4) {
            int   s0 = __shfl_sync(FULL, s_l, k + 0);
            int   s1 = __shfl_sync(FULL, s_l, k + 1);
            int   s2 = __shfl_sync(FULL, s_l, k + 2);
            int   s3 = __shfl_sync(FULL, s_l, k + 3);
            float x0 = __shfl_sync(FULL, ex_l, k + 0);
            float x1 = __shfl_sync(FULL, ex_l, k + 1);
            float x2 = __shfl_sync(FULL, ex_l, k + 2);
            float x3 = __shfl_sync(FULL, ex_l, k + 3);
            float2 v0 = __half22float2(h[(size_t)s0 * 32 + lane]);
            float2 v1 = __half22float2(h[(size_t)s1 * 32 + lane]);
            float2 v2 = __half22float2(h[(size_t)s2 * 32 + lane]);
            float2 v3 = __half22float2(h[(size_t)s3 * 32 + lane]);
            accx = fmaf(x0, v0.x, accx); accy = fmaf(x0, v0.y, accy);
            accx = fmaf(x1, v1.x, accx); accy = fmaf(x1, v1.y, accy);
            accx = fmaf(x2, v2.x, accx); accy = fmaf(x2, v2.y, accy);
            accx = fmaf(x3, v3.x, accx); accy = fmaf(x3, v3.y, accy);
        }
        for (; k < deg; k++) {
            float ex = __shfl_sync(FULL, ex_l, k);
            int   s  = __shfl_sync(FULL, s_l, k);
            float2 hv = __half22float2(h[(size_t)s * 32 + lane]);
            accx = fmaf(ex, hv.x, accx);
            accy = fmaf(ex, hv.y, accy);
        }
    } else {
        float m = m_self;
        for (int j = lane; j < deg; j += 32) {
            int s = g_csrc[row + j];
            m = fmaxf(m, lrelu(g_als[s] + aldd));
        }
#pragma unroll
        for (int off = 16; off; off >>= 1) m = fmaxf(m, __shfl_xor_sync(FULL, m, off));
        exs = __expf(m_self - m);
        accx = exs * hv0.x;
        accy = exs * hv0.y;
        den = 0.f;
        for (int base = 0; base < deg; base += 32) {
            int jl = base + lane;
            int s_l = 0; float ex_l = 0.f;
            if (jl < deg) {
                s_l = g_csrc[row + jl];
                ex_l = __expf(lrelu(g_als[s_l] + aldd) - m);
            }
            den += ex_l;
            int cnt = deg - base; if (cnt > 32) cnt = 32;
            int k = 0;
            for (; k + 4 <= cnt; k += 4) {
                int   s0 = __shfl_sync(FULL, s_l, k + 0);
                int   s1 = __shfl_sync(FULL, s_l, k + 1);
                int   s2 = __shfl_sync(FULL, s_l, k + 2);
                int   s3 = __shfl_sync(FULL, s_l, k + 3);
                float x0 = __shfl_sync(FULL, ex_l, k + 0);
                float x1 = __shfl_sync(FULL, ex_l, k + 1);
                float x2 = __shfl_sync(FULL, ex_l, k + 2);
                float x3 = __shfl_sync(FULL, ex_l, k + 3);
                float2 v0 = __half22float2(h[(size_t)s0 * 32 + lane]);
                float2 v1 = __half22float2(h[(size_t)s1 * 32 + lane]);
                float2 v2 = __half22float2(h[(size_t)s2 * 32 + lane]);
                float2 v3 = __half22float2(h[(size_t)s3 * 32 + lane]);
                accx = fmaf(x0, v0.x, accx); accy = fmaf(x0, v0.y, accy);
                accx = fmaf(x1, v1.x, accx); accy = fmaf(x1, v1.y, accy);
                accx = fmaf(x2, v2.x, accx); accy = fmaf(x2, v2.y, accy);
                accx = fmaf(x3, v3.x, accx); accy = fmaf(x3, v3.y, accy);
            }
            for (; k < cnt; k++) {
                float ex = __shfl_sync(FULL, ex_l, k);
                int   s  = __shfl_sync(FULL, s_l, k);
                float2 hv = __half22float2(h[(size_t)s * 32 + lane]);
                accx = fmaf(ex, hv.x, accx);
                accy = fmaf(ex, hv.y, accy);
            }
        }
    }
#pragma unroll
    for (int off = 16; off; off >>= 1) den += __shfl_xor_sync(FULL, den, off);
    den += exs;   // self-loop term (warp-uniform)
    float inv = 1.f / den;
    float2 r;
    r.x = elu_(accx * inv + bs[2 * lane + 0]);
    r.y = elu_(accy * inv + bs[2 * lane + 1]);
    return r;
}

// ---------------- layer-1 gather: writes fp32 g_hx ----------------
__global__ __launch_bounds__(256) void gather_kernel(const float* __restrict__ bias) {
    __shared__ float bs[64];
    if (threadIdx.x < 64) bs[threadIdx.x] = bias[threadIdx.x];
    __syncthreads();
    int d = (blockIdx.x * 256 + threadIdx.x) >> 5;
    int lane = threadIdx.x & 31;
    if (d >= NN) return;
    float2 o = gather_row(d, lane, bs);
    *(float2*)(g_hx + (size_t)d * HH + 2 * lane) = o;
}

// ---------------- layer-2 gather + MLP head + pool, fully fused ----------------
__global__ __launch_bounds__(256) void gather_mlp_pool(
    const float* __restrict__ bias, const float* __restrict__ mw1,
    const float* __restrict__ mb1, const float* __restrict__ mw2,
    const float* __restrict__ mb2, const void* __restrict__ batch,
    float* __restrict__ out)
{
    __shared__ float bs[64];
    __shared__ float2 mw1s[64 * 32];   // [k][c-pair]: reinterpret of row-major mw1
    __shared__ float  mw2s[64 * CC];
    __shared__ float  mb1s[64], mb2s[CC];
    int tid = threadIdx.x;
    if (tid < 64) { bs[tid] = bias[tid]; mb1s[tid] = mb1[tid]; }
    if (tid < CC) mb2s[tid] = mb2[tid];
    {
        const float2* m1 = (const float2*)mw1;
        for (int i = tid; i < 64 * 32; i += 256) mw1s[i] = m1[i];
        for (int i = tid; i < 64 * CC; i += 256) mw2s[i] = mw2[i];
    }
    __syncthreads();

    int d = (blockIdx.x * 256 + tid) >> 5;
    int lane = tid & 31;
    if (d >= NN) return;
    const unsigned FULL = 0xffffffffu;

    float2 hx = gather_row(d, lane, bs);   // features 2*lane, 2*lane+1 of node d

    // hidden = relu(hx_row @ mw1 + mb1); lane computes hidden cols 2*lane, 2*lane+1
    float hid0 = mb1s[2 * lane], hid1 = mb1s[2 * lane + 1];
#pragma unroll 8
    for (int k = 0; k < 32; k++) {
        float ax = __shfl_sync(FULL, hx.x, k);   // feature 2k
        float ay = __shfl_sync(FULL, hx.y, k);   // feature 2k+1
        float2 w0 = mw1s[(2 * k) * 32 + lane];
        float2 w1 = mw1s[(2 * k + 1) * 32 + lane];
        hid0 = fmaf(ax, w0.x, hid0); hid1 = fmaf(ax, w0.y, hid1);
        hid0 = fmaf(ay, w1.x, hid0); hid1 = fmaf(ay, w1.y, hid1);
    }
    hid0 = fmaxf(hid0, 0.f);
    hid1 = fmaxf(hid1, 0.f);

    // out10 = hidden @ mw2 + mb2; per-lane partials then butterfly reduce
    float p[CC];
#pragma unroll
    for (int c = 0; c < CC; c++) {
        float t = (lane == 0) ? mb2s[c] : 0.f;
        t = fmaf(hid0, mw2s[(2 * lane) * CC + c], t);
        t = fmaf(hid1, mw2s[(2 * lane + 1) * CC + c], t);
        p[c] = t;
    }
#pragma unroll
    for (int c = 0; c < CC; c++) {
#pragma unroll
        for (int off = 16; off; off >>= 1) p[c] += __shfl_xor_sync(FULL, p[c], off);
    }
    if (lane == 0) {
        int g;
        if (g_i64) g = (int)((const long long*)batch)[d];
        else       g = ((const int*)batch)[d];
#pragma unroll
        for (int c = 0; c < CC; c++) atomicAdd(&out[g * CC + c], p[c]);
    }
}

// ---------------- static stream/events for fork-join overlap ----------------
// Created at static-init time (before the harness's memory checkpoints; no device
// allocation happens inside kernel_launch).
static cudaStream_t g_s1;
static cudaEvent_t  g_ev1, g_ev2;
namespace {
struct _StreamInit {
    _StreamInit() {
        cudaStreamCreateWithFlags(&g_s1, cudaStreamNonBlocking);
        cudaEventCreateWithFlags(&g_ev1, cudaEventDisableTiming);
        cudaEventCreateWithFlags(&g_ev2, cudaEventDisableTiming);
    }
};
static _StreamInit _si;
}

// ---------------- launch ----------------
extern "C" void kernel_launch(void* const* d_in, const int* in_sizes, int n_in,
                              void* d_out, int out_size) {
    const float* x     = (const float*)d_in[0];
    const int*   ei_w  = (const int*)d_in[1];
    const void*  batch = d_in[2];
    const float* W1  = (const float*)d_in[3];
    const float* as1 = (const float*)d_in[4];
    const float* ad1 = (const float*)d_in[5];
    const float* b1  = (const float*)d_in[6];
    const float* W2  = (const float*)d_in[7];
    const float* as2 = (const float*)d_in[8];
    const float* ad2 = (const float*)d_in[9];
    const float* b2  = (const float*)d_in[10];
    const float* mw1 = (const float*)d_in[11];
    const float* mb1 = (const float*)d_in[12];
    const float* mw2 = (const float*)d_in[13];
    const float* mb2 = (const float*)d_in[14];
    float* out = (float*)d_out;

    int gb = (NN + 127) / 128;
    int nb = (NN + 255) / 256;
    int eb = (EE + 255) / 256;
    int wb = ((NN * 32) + 255) / 256;

    // fork: gemm1 (depends only on x/W1) runs concurrently with the CSR build
    cudaEventRecord(g_ev1, 0);
    cudaStreamWaitEvent(g_s1, g_ev1, 0);
    gemm_gat<<<gb, 128, 0, g_s1>>>(0, x, W1, as1, ad1);
    cudaEventRecord(g_ev2, g_s1);

    zero_kernel<<<nb, 256>>>(ei_w, out);
    prep_kernel<<<eb, 256>>>(ei_w);
    scan1_kernel<<<NB1, 1024>>>();
    scan2_kernel<<<1, 128>>>();
    scan3_kernel<<<nb, 256>>>();
    fill_kernel<<<eb, 256>>>(ei_w);

    // join
    cudaStreamWaitEvent(0, g_ev2, 0);

    gather_kernel<<<wb, 256>>>(b1);
    gemm_gat<<<gb, 128>>>(1, x, W2, as2, ad2);
    gather_mlp_pool<<<wb, 256>>>(b2, mw1, mb1, mw2, mb2, batch, out);
}

// round 10
// speedup vs baseline: 1.7559x; 1.7559x over previous
#include <cuda_runtime.h>
#include <cuda_fp16.h>

#define NN 100000
#define EE 1600000
#define HH 64
#define GG 128
#define CC 10
#define NB1 98   // ceil(NN/1024)

// ---------------- scratch (device globals: no runtime allocation) ----------------
__device__ int     g_csrc[EE];
__device__ int     g_deg[NN];
__device__ int     g_rowptr[NN];
__device__ int     g_cursor[NN];
__device__ int     g_incl[NN];
__device__ int     g_bsum[128];
__device__ __half2 g_h1h[(size_t)NN * 32];   // fp16 pre-activation features (both layers)
__device__ float   g_hx[(size_t)NN * HH];    // post softmax+bias+elu (fp32, both layers)
__device__ float   g_als[NN];
__device__ float   g_ald[NN];
__device__ int     g_i64;

__device__ __forceinline__ float lrelu(float x) { return x > 0.f ? x : 0.2f * x; }
__device__ __forceinline__ float elu_(float x)  { return x > 0.f ? x : expm1f(x); }

// ---------------- zero + dtype detect (int64 indices have zero high words) ----------
__global__ void zero_kernel(const int* __restrict__ ei_w, float* __restrict__ out) {
    int i = blockIdx.x * blockDim.x + threadIdx.x;
    if (i == 0) {
        int flag = 1;
        for (int k = 0; k < 64; k++)
            if (ei_w[2 * k + 1] != 0) flag = 0;
        g_i64 = flag;
    }
    if (i < NN) g_deg[i] = 0;
    if (i < GG * CC) out[i] = 0.f;
}

__global__ void prep_kernel(const int* __restrict__ ei_w) {
    int i = blockIdx.x * blockDim.x + threadIdx.x;
    if (i >= EE) return;
    int d;
    if (g_i64) d = (int)((const long long*)ei_w)[EE + i];
    else       d = ei_w[EE + i];
    atomicAdd(&g_deg[d], 1);
}

__global__ void scan1_kernel() {
    __shared__ int sm[1024];
    int t = threadIdx.x;
    int i = blockIdx.x * 1024 + t;
    int v = (i < NN) ? g_deg[i] : 0;
    sm[t] = v;
    __syncthreads();
#pragma unroll
    for (int off = 1; off < 1024; off <<= 1) {
        int x = (t >= off) ? sm[t - off] : 0;
        __syncthreads();
        sm[t] += x;
        __syncthreads();
    }
    if (i < NN) g_incl[i] = sm[t];
    if (t == 1023) g_bsum[blockIdx.x] = sm[t];
}

__global__ void scan2_kernel() {
    __shared__ int sm[128];
    int t = threadIdx.x;
    int v = (t < NB1) ? g_bsum[t] : 0;
    sm[t] = v;
    __syncthreads();
#pragma unroll
    for (int off = 1; off < 128; off <<= 1) {
        int x = (t >= off) ? sm[t - off] : 0;
        __syncthreads();
        sm[t] += x;
        __syncthreads();
    }
    if (t < NB1) g_bsum[t] = sm[t] - v;   // exclusive
}

__global__ void scan3_kernel() {
    int i = blockIdx.x * blockDim.x + threadIdx.x;
    if (i >= NN) return;
    int excl = g_incl[i] - g_deg[i] + g_bsum[i >> 10];
    g_rowptr[i] = excl;
    g_cursor[i] = excl;
}

__global__ void fill_kernel(const int* __restrict__ ei_w) {
    int i = blockIdx.x * blockDim.x + threadIdx.x;
    if (i >= EE) return;
    int s, d;
    if (g_i64) {
        const long long* e64 = (const long long*)ei_w;
        s = (int)e64[i];
        d = (int)e64[EE + i];
    } else {
        s = ei_w[i];
        d = ei_w[EE + i];
    }
    int slot = atomicAdd(&g_cursor[d], 1);
    g_csrc[slot] = s;
}

// ---------------- GEMM (Nx64 @ 64x64) + epilogue: fp16 h row + attention halves -----
// mode 0: read external x; mode 1: read g_hx
__global__ __launch_bounds__(128) void gemm_gat(
    int mode, const float* __restrict__ xext, const float* __restrict__ W,
    const float* __restrict__ avs, const float* __restrict__ avd)
{
    __shared__ float4 Ws[64 * 16];
    __shared__ float as_s[64], ad_s[64];
    int tid = threadIdx.x;
    const float4* W4 = (const float4*)W;
    for (int i = tid; i < 64 * 16; i += 128) Ws[i] = W4[i];
    if (tid < 64) { as_s[tid] = avs[tid]; ad_s[tid] = avd[tid]; }
    __syncthreads();

    int row = blockIdx.x * 128 + tid;
    if (row >= NN) return;
    size_t base = (size_t)row * HH;

    float o[64];
#pragma unroll
    for (int c = 0; c < 64; c++) o[c] = 0.f;

    const float* xin = mode ? g_hx : xext;
    const float4* xp = (const float4*)(xin + base);
#pragma unroll 4
    for (int k4 = 0; k4 < 16; k4++) {
        float4 v = xp[k4];
        float xk[4] = {v.x, v.y, v.z, v.w};
#pragma unroll
        for (int kk = 0; kk < 4; kk++) {
            int k = 4 * k4 + kk;
            float xv = xk[kk];
#pragma unroll
            for (int c4 = 0; c4 < 16; c4++) {
                float4 w = Ws[k * 16 + c4];
                o[4 * c4 + 0] = fmaf(xv, w.x, o[4 * c4 + 0]);
                o[4 * c4 + 1] = fmaf(xv, w.y, o[4 * c4 + 1]);
                o[4 * c4 + 2] = fmaf(xv, w.z, o[4 * c4 + 2]);
                o[4 * c4 + 3] = fmaf(xv, w.w, o[4 * c4 + 3]);
            }
        }
    }

    // epilogue: fp32 attention halves, fp16 h row (halves gather traffic)
    float als = 0.f, ald = 0.f;
    __half2 hrow[32];
#pragma unroll
    for (int c2 = 0; c2 < 32; c2++) {
        float a = o[2 * c2], b = o[2 * c2 + 1];
        hrow[c2] = __floats2half2_rn(a, b);
        als += a * as_s[2 * c2] + b * as_s[2 * c2 + 1];
        ald += a * ad_s[2 * c2] + b * ad_s[2 * c2 + 1];
    }
    float4* dst = (float4*)(g_h1h + (size_t)row * 32);
    const float4* srcv = (const float4*)hrow;
#pragma unroll
    for (int i = 0; i < 8; i++) dst[i] = srcv[i];

    g_als[row] = als;
    g_ald[row] = ald;
}

// ---------------- warp-per-dst gather: softmax + weighted sum + bias + elu ----------
// h rows are fp16 (one half2 per lane); all accumulation in fp32.
__global__ __launch_bounds__(256) void gather_kernel(const float* __restrict__ bias) {
    __shared__ float bs[64];
    if (threadIdx.x < 64) bs[threadIdx.x] = bias[threadIdx.x];
    __syncthreads();

    int d = (blockIdx.x * 256 + threadIdx.x) >> 5;
    int lane = threadIdx.x & 31;
    if (d >= NN) return;

    const __half2* __restrict__ h = g_h1h;
    const unsigned FULL = 0xffffffffu;
    float aldd = g_ald[d];
    float m_self = lrelu(g_als[d] + aldd);
    int row = g_rowptr[d];
    int deg = g_deg[d];

    float2 hv0 = __half22float2(h[(size_t)d * 32 + lane]);
    float accx, accy, den, exs;

    if (deg <= 32) {
        // ---- fast path: one register-resident pass ----
        int   s_l = 0;
        float e_l = -1e30f;
        if (lane < deg) {
            s_l = g_csrc[row + lane];
            e_l = lrelu(g_als[s_l] + aldd);
        }
        float m = fmaxf(m_self, e_l);
#pragma unroll
        for (int off = 16; off; off >>= 1) m = fmaxf(m, __shfl_xor_sync(FULL, m, off));
        float ex_l = (lane < deg) ? __expf(e_l - m) : 0.f;
        den = ex_l;
        exs = __expf(m_self - m);
        accx = exs * hv0.x;
        accy = exs * hv0.y;
        int k = 0;
        for (; k + 4 <= deg; k += 4) {
            int   s0 = __shfl_sync(FULL, s_l, k + 0);
            int   s1 = __shfl_sync(FULL, s_l, k + 1);
            int   s2 = __shfl_sync(FULL, s_l, k + 2);
            int   s3 = __shfl_sync(FULL, s_l, k + 3);
            float x0 = __shfl_sync(FULL, ex_l, k + 0);
            float x1 = __shfl_sync(FULL, ex_l, k + 1);
            float x2 = __shfl_sync(FULL, ex_l, k + 2);
            float x3 = __shfl_sync(FULL, ex_l, k + 3);
            float2 v0 = __half22float2(h[(size_t)s0 * 32 + lane]);
            float2 v1 = __half22float2(h[(size_t)s1 * 32 + lane]);
            float2 v2 = __half22float2(h[(size_t)s2 * 32 + lane]);
            float2 v3 = __half22float2(h[(size_t)s3 * 32 + lane]);
            accx = fmaf(x0, v0.x, accx); accy = fmaf(x0, v0.y, accy);
            accx = fmaf(x1, v1.x, accx); accy = fmaf(x1, v1.y, accy);
            accx = fmaf(x2, v2.x, accx); accy = fmaf(x2, v2.y, accy);
            accx = fmaf(x3, v3.x, accx); accy = fmaf(x3, v3.y, accy);
        }
        for (; k < deg; k++) {
            float ex = __shfl_sync(FULL, ex_l, k);
            int   s  = __shfl_sync(FULL, s_l, k);
            float2 hv = __half22float2(h[(size_t)s * 32 + lane]);
            accx = fmaf(ex, hv.x, accx);
            accy = fmaf(ex, hv.y, accy);
        }
    } else {
        // ---- general two-pass path (rare for Poisson(16) degrees) ----
        float m = m_self;
        for (int j = lane; j < deg; j += 32) {
            int s = g_csrc[row + j];
            m = fmaxf(m, lrelu(g_als[s] + aldd));
        }
#pragma unroll
        for (int off = 16; off; off >>= 1) m = fmaxf(m, __shfl_xor_sync(FULL, m, off));
        exs = __expf(m_self - m);
        accx = exs * hv0.x;
        accy = exs * hv0.y;
        den = 0.f;
        for (int base = 0; base < deg; base += 32) {
            int jl = base + lane;
            int s_l = 0; float ex_l = 0.f;
            if (jl < deg) {
                s_l = g_csrc[row + jl];
                ex_l = __expf(lrelu(g_als[s_l] + aldd) - m);
            }
            den += ex_l;
            int cnt = deg - base; if (cnt > 32) cnt = 32;
            int k = 0;
            for (; k + 4 <= cnt; k += 4) {
                int   s0 = __shfl_sync(FULL, s_l, k + 0);
                int   s1 = __shfl_sync(FULL, s_l, k + 1);
                int   s2 = __shfl_sync(FULL, s_l, k + 2);
                int   s3 = __shfl_sync(FULL, s_l, k + 3);
                float x0 = __shfl_sync(FULL, ex_l, k + 0);
                float x1 = __shfl_sync(FULL, ex_l, k + 1);
                float x2 = __shfl_sync(FULL, ex_l, k + 2);
                float x3 = __shfl_sync(FULL, ex_l, k + 3);
                float2 v0 = __half22float2(h[(size_t)s0 * 32 + lane]);
                float2 v1 = __half22float2(h[(size_t)s1 * 32 + lane]);
                float2 v2 = __half22float2(h[(size_t)s2 * 32 + lane]);
                float2 v3 = __half22float2(h[(size_t)s3 * 32 + lane]);
                accx = fmaf(x0, v0.x, accx); accy = fmaf(x0, v0.y, accy);
                accx = fmaf(x1, v1.x, accx); accy = fmaf(x1, v1.y, accy);
                accx = fmaf(x2, v2.x, accx); accy = fmaf(x2, v2.y, accy);
                accx = fmaf(x3, v3.x, accx); accy = fmaf(x3, v3.y, accy);
            }
            for (; k < cnt; k++) {
                float ex = __shfl_sync(FULL, ex_l, k);
                int   s  = __shfl_sync(FULL, s_l, k);
                float2 hv = __half22float2(h[(size_t)s * 32 + lane]);
                accx = fmaf(ex, hv.x, accx);
                accy = fmaf(ex, hv.y, accy);
            }
        }
    }
#pragma unroll
    for (int off = 16; off; off >>= 1) den += __shfl_xor_sync(FULL, den, off);
    den += exs;   // self-loop term (warp-uniform)
    float inv = 1.f / den;
    float2 o;
    o.x = elu_(accx * inv + bs[2 * lane + 0]);
    o.y = elu_(accy * inv + bs[2 * lane + 1]);
    *(float2*)(g_hx + (size_t)d * HH + 2 * lane) = o;
}

// ---------------- MLP head + pooled output (sorted-batch warp-uniform pooling) ------
__global__ __launch_bounds__(128) void final_kernel(
    const float* __restrict__ mw1, const float* __restrict__ mb1,
    const float* __restrict__ mw2, const float* __restrict__ mb2,
    const void* __restrict__ batch, float* __restrict__ out)
{
    __shared__ float mw1T[64 * 64];
    __shared__ float mw2s[64 * CC];
    __shared__ float mb1s[64], mb2s[CC];
    int tid = threadIdx.x;
    for (int i = tid; i < 64 * 64; i += 128) {
        int c = i >> 6, j = i & 63;
        mw1T[j * 64 + c] = mw1[i];
    }
    for (int i = tid; i < 64 * CC; i += 128) mw2s[i] = mw2[i];
    if (tid < 64) mb1s[tid] = mb1[tid];
    if (tid < CC) mb2s[tid] = mb2[tid];
    __syncthreads();

    int row = blockIdx.x * 128 + tid;
    int lane = tid & 31;
    bool active = row < NN;

    float o[CC];
#pragma unroll
    for (int c = 0; c < CC; c++) o[c] = 0.f;
    int g = 0;

    if (active) {
        size_t base = (size_t)row * HH;
        float hf[64];
        const float4* hp = (const float4*)(g_hx + base);
#pragma unroll
        for (int i = 0; i < 16; i++) {
            float4 h = hp[i];
            hf[4 * i + 0] = h.x; hf[4 * i + 1] = h.y;
            hf[4 * i + 2] = h.z; hf[4 * i + 3] = h.w;
        }
#pragma unroll
        for (int c = 0; c < CC; c++) o[c] = mb2s[c];
        const float4* m1 = (const float4*)mw1T;
#pragma unroll 4
        for (int j = 0; j < 64; j++) {
            float t = mb1s[j];
#pragma unroll
            for (int c4 = 0; c4 < 16; c4++) {
                float4 w = m1[j * 16 + c4];
                t = fmaf(hf[4 * c4 + 0], w.x, t);
                t = fmaf(hf[4 * c4 + 1], w.y, t);
                t = fmaf(hf[4 * c4 + 2], w.z, t);
                t = fmaf(hf[4 * c4 + 3], w.w, t);
            }
            t = fmaxf(t, 0.f);
#pragma unroll
            for (int c = 0; c < CC; c++) o[c] = fmaf(t, mw2s[j * CC + c], o[c]);
        }
        if (g_i64) g = (int)((const long long*)batch)[row];
        else       g = ((const int*)batch)[row];
    }

    // batch is sorted -> most warps graph-uniform: in-warp reduce, 1 atomic/col/warp
    unsigned mask = 0xffffffffu;
    int g0 = __shfl_sync(mask, g, 0);
    bool uni = __all_sync(mask, g == g0);
    if (uni) {
#pragma unroll
        for (int c = 0; c < CC; c++) {
            float v = o[c];
#pragma unroll
            for (int off = 16; off > 0; off >>= 1) v += __shfl_xor_sync(mask, v, off);
            if (lane == 0) atomicAdd(&out[g0 * CC + c], v);
        }
    } else {
        if (active) {
#pragma unroll
            for (int c = 0; c < CC; c++) atomicAdd(&out[g * CC + c], o[c]);
        }
    }
}

// ---------------- launch (single stream, sequential — no fork-join) ----------------
extern "C" void kernel_launch(void* const* d_in, const int* in_sizes, int n_in,
                              void* d_out, int out_size) {
    const float* x     = (const float*)d_in[0];
    const int*   ei_w  = (const int*)d_in[1];
    const void*  batch = d_in[2];
    const float* W1  = (const float*)d_in[3];
    const float* as1 = (const float*)d_in[4];
    const float* ad1 = (const float*)d_in[5];
    const float* b1  = (const float*)d_in[6];
    const float* W2  = (const float*)d_in[7];
    const float* as2 = (const float*)d_in[8];
    const float* ad2 = (const float*)d_in[9];
    const float* b2  = (const float*)d_in[10];
    const float* mw1 = (const float*)d_in[11];
    const float* mb1 = (const float*)d_in[12];
    const float* mw2 = (const float*)d_in[13];
    const float* mb2 = (const float*)d_in[14];
    float* out = (float*)d_out;

    int gb = (NN + 127) / 128;
    int nb = (NN + 255) / 256;
    int eb = (EE + 255) / 256;
    int wb = ((NN * 32) + 255) / 256;

    zero_kernel<<<nb, 256>>>(ei_w, out);
    prep_kernel<<<eb, 256>>>(ei_w);
    scan1_kernel<<<NB1, 1024>>>();
    scan2_kernel<<<1, 128>>>();
    scan3_kernel<<<nb, 256>>>();
    fill_kernel<<<eb, 256>>>(ei_w);

    gemm_gat<<<gb, 128>>>(0, x, W1, as1, ad1);
    gather_kernel<<<wb, 256>>>(b1);

    gemm_gat<<<gb, 128>>>(1, x, W2, as2, ad2);
    gather_kernel<<<wb, 256>>>(b2);

    final_kernel<<<gb, 128>>>(mw1, mb1, mw2, mb2, batch, out);
}

// round 11
// speedup vs baseline: 1.8193x; 1.0361x over previous
#include <cuda_runtime.h>
#include <cuda_fp16.h>

#define NN 100000
#define EE 1600000
#define HH 64
#define GG 128
#define CC 10
#define NB1 98   // ceil(NN/1024)

typedef unsigned long long ull;

// ---------------- scratch (device globals: no runtime allocation) ----------------
__device__ int     g_csrc[EE];
__device__ int     g_deg[NN];
__device__ int     g_rowptr[NN];
__device__ int     g_cursor[NN];
__device__ int     g_incl[NN];
__device__ int     g_bsum[128];
__device__ __half2 g_h1h[(size_t)NN * 32];   // fp16 pre-activation features (both layers)
__device__ float   g_hx[(size_t)NN * HH];    // post softmax+bias+elu (fp32, both layers)
__device__ float   g_als[NN];
__device__ float   g_ald[NN];
__device__ int     g_i64;

__device__ __forceinline__ float lrelu(float x) { return x > 0.f ? x : 0.2f * x; }
__device__ __forceinline__ float elu_(float x)  { return x > 0.f ? x : expm1f(x); }

// ---- packed fp32x2 helpers (Blackwell FFMA2; bit-identical fp32 per lane) ----
__device__ __forceinline__ ull pack2(float lo, float hi) {
    ull r;
    asm("mov.b64 %0, {%1, %2};" : "=l"(r) : "f"(lo), "f"(hi));
    return r;
}
__device__ __forceinline__ void unpack2(ull v, float& lo, float& hi) {
    asm("mov.b64 {%0, %1}, %2;" : "=f"(lo), "=f"(hi) : "l"(v));
}
__device__ __forceinline__ ull fma2(ull a, ull b, ull c) {
    ull d;
    asm("fma.rn.f32x2 %0, %1, %2, %3;" : "=l"(d) : "l"(a), "l"(b), "l"(c));
    return d;
}

// ---------------- zero + dtype detect (int64 indices have zero high words) ----------
__global__ void zero_kernel(const int* __restrict__ ei_w, float* __restrict__ out) {
    int i = blockIdx.x * blockDim.x + threadIdx.x;
    if (i == 0) {
        int flag = 1;
        for (int k = 0; k < 64; k++)
            if (ei_w[2 * k + 1] != 0) flag = 0;
        g_i64 = flag;
    }
    if (i < NN) g_deg[i] = 0;
    if (i < GG * CC) out[i] = 0.f;
}

__global__ void prep_kernel(const int* __restrict__ ei_w) {
    int i = blockIdx.x * blockDim.x + threadIdx.x;
    if (i >= EE) return;
    int d;
    if (g_i64) d = (int)((const long long*)ei_w)[EE + i];
    else       d = ei_w[EE + i];
    atomicAdd(&g_deg[d], 1);
}

__global__ void scan1_kernel() {
    __shared__ int sm[1024];
    int t = threadIdx.x;
    int i = blockIdx.x * 1024 + t;
    int v = (i < NN) ? g_deg[i] : 0;
    sm[t] = v;
    __syncthreads();
#pragma unroll
    for (int off = 1; off < 1024; off <<= 1) {
        int x = (t >= off) ? sm[t - off] : 0;
        __syncthreads();
        sm[t] += x;
        __syncthreads();
    }
    if (i < NN) g_incl[i] = sm[t];
    if (t == 1023) g_bsum[blockIdx.x] = sm[t];
}

// scan3 with the (tiny) block-sum scan inlined — removes the scan2 launch
__global__ void scan3_kernel() {
    __shared__ int sb[128];
    int t = threadIdx.x;
    if (t < 128) sb[t] = (t < NB1) ? g_bsum[t] : 0;
    __syncthreads();
#pragma unroll
    for (int off = 1; off < 128; off <<= 1) {
        int x = 0;
        if (t < 128 && t >= off) x = sb[t - off];
        __syncthreads();
        if (t < 128) sb[t] += x;
        __syncthreads();
    }
    int i = blockIdx.x * blockDim.x + t;
    if (i >= NN) return;
    int b = i >> 10;
    int bexcl = (b == 0) ? 0 : sb[b - 1];   // exclusive from inclusive scan
    int excl = g_incl[i] - g_deg[i] + bexcl;
    g_rowptr[i] = excl;
    g_cursor[i] = excl;
}

__global__ void fill_kernel(const int* __restrict__ ei_w) {
    int i = blockIdx.x * blockDim.x + threadIdx.x;
    if (i >= EE) return;
    int s, d;
    if (g_i64) {
        const long long* e64 = (const long long*)ei_w;
        s = (int)e64[i];
        d = (int)e64[EE + i];
    } else {
        s = ei_w[i];
        d = ei_w[EE + i];
    }
    int slot = atomicAdd(&g_cursor[d], 1);
    g_csrc[slot] = s;
}

// ---------------- GEMM (Nx64 @ 64x64), packed f32x2 FMA + fp16-h epilogue ----------
// mode 0: read external x; mode 1: read g_hx
__global__ __launch_bounds__(128) void gemm_gat(
    int mode, const float* __restrict__ xext, const float* __restrict__ W,
    const float* __restrict__ avs, const float* __restrict__ avd)
{
    __shared__ __align__(16) float4 Ws[64 * 16];
    __shared__ float as_s[64], ad_s[64];
    int tid = threadIdx.x;
    const float4* W4 = (const float4*)W;
    for (int i = tid; i < 64 * 16; i += 128) Ws[i] = W4[i];
    if (tid < 64) { as_s[tid] = avs[tid]; ad_s[tid] = avd[tid]; }
    __syncthreads();

    int row = blockIdx.x * 128 + tid;
    if (row >= NN) return;
    size_t base = (size_t)row * HH;

    ull o2[32];
#pragma unroll
    for (int c = 0; c < 32; c++) o2[c] = 0ull;

    const float* xin = mode ? g_hx : xext;
    const float4* xp = (const float4*)(xin + base);
    const ulonglong2* Ws2 = (const ulonglong2*)Ws;
#pragma unroll 4
    for (int k4 = 0; k4 < 16; k4++) {
        float4 v = xp[k4];
        float xk[4] = {v.x, v.y, v.z, v.w};
#pragma unroll
        for (int kk = 0; kk < 4; kk++) {
            int k = 4 * k4 + kk;
            ull xv2 = pack2(xk[kk], xk[kk]);
#pragma unroll
            for (int c4 = 0; c4 < 16; c4++) {
                ulonglong2 w = Ws2[k * 16 + c4];
                o2[2 * c4 + 0] = fma2(w.x, xv2, o2[2 * c4 + 0]);
                o2[2 * c4 + 1] = fma2(w.y, xv2, o2[2 * c4 + 1]);
            }
        }
    }

    // epilogue: fp32 attention halves, fp16 h row
    float als = 0.f, ald = 0.f;
    __half2 hrow[32];
#pragma unroll
    for (int c2 = 0; c2 < 32; c2++) {
        float a, b;
        unpack2(o2[c2], a, b);
        hrow[c2] = __floats2half2_rn(a, b);
        als += a * as_s[2 * c2] + b * as_s[2 * c2 + 1];
        ald += a * ad_s[2 * c2] + b * ad_s[2 * c2 + 1];
    }
    float4* dst = (float4*)(g_h1h + (size_t)row * 32);
    const float4* srcv = (const float4*)hrow;
#pragma unroll
    for (int i = 0; i < 8; i++) dst[i] = srcv[i];

    g_als[row] = als;
    g_ald[row] = ald;
}

// ---------------- warp-per-dst gather: softmax + weighted sum + bias + elu ----------
__global__ __launch_bounds__(256) void gather_kernel(const float* __restrict__ bias) {
    __shared__ float bs[64];
    if (threadIdx.x < 64) bs[threadIdx.x] = bias[threadIdx.x];
    __syncthreads();

    int d = (blockIdx.x * 256 + threadIdx.x) >> 5;
    int lane = threadIdx.x & 31;
    if (d >= NN) return;

    const __half2* __restrict__ h = g_h1h;
    const unsigned FULL = 0xffffffffu;
    float aldd = g_ald[d];
    float m_self = lrelu(g_als[d] + aldd);
    int row = g_rowptr[d];
    int deg = g_deg[d];

    float2 hv0 = __half22float2(h[(size_t)d * 32 + lane]);
    float accx, accy, den, exs;

    if (deg <= 32) {
        int   s_l = 0;
        float e_l = -1e30f;
        if (lane < deg) {
            s_l = g_csrc[row + lane];
            e_l = lrelu(g_als[s_l] + aldd);
        }
        float m = fmaxf(m_self, e_l);
#pragma unroll
        for (int off = 16; off; off >>= 1) m = fmaxf(m, __shfl_xor_sync(FULL, m, off));
        float ex_l = (lane < deg) ? __expf(e_l - m) : 0.f;
        den = ex_l;
        exs = __expf(m_self - m);
        accx = exs * hv0.x;
        accy = exs * hv0.y;
        int k = 0;
        for (; k + 4 <= deg; k += 4) {
            int   s0 = __shfl_sync(FULL, s_l, k + 0);
            int   s1 = __shfl_sync(FULL, s_l, k + 1);
            int   s2 = __shfl_sync(FULL, s_l, k + 2);
            int   s3 = __shfl_sync(FULL, s_l, k + 3);
            float x0 = __shfl_sync(FULL, ex_l, k + 0);
            float x1 = __shfl_sync(FULL, ex_l, k + 1);
            float x2 = __shfl_sync(FULL, ex_l, k + 2);
            float x3 = __shfl_sync(FULL, ex_l, k + 3);
            float2 v0 = __half22float2(h[(size_t)s0 * 32 + lane]);
            float2 v1 = __half22float2(h[(size_t)s1 * 32 + lane]);
            float2 v2 = __half22float2(h[(size_t)s2 * 32 + lane]);
            float2 v3 = __half22float2(h[(size_t)s3 * 32 + lane]);
            accx = fmaf(x0, v0.x, accx); accy = fmaf(x0, v0.y, accy);
            accx = fmaf(x1, v1.x, accx); accy = fmaf(x1, v1.y, accy);
            accx = fmaf(x2, v2.x, accx); accy = fmaf(x2, v2.y, accy);
            accx = fmaf(x3, v3.x, accx); accy = fmaf(x3, v3.y, accy);
        }
        for (; k < deg; k++) {
            float ex = __shfl_sync(FULL, ex_l, k);
            int   s  = __shfl_sync(FULL, s_l, k);
            float2 hv = __half22float2(h[(size_t)s * 32 + lane]);
            accx = fmaf(ex, hv.x, accx);
            accy = fmaf(ex, hv.y, accy);
        }
    } else {
        float m = m_self;
        for (int j = lane; j < deg; j += 32) {
            int s = g_csrc[row + j];
            m = fmaxf(m, lrelu(g_als[s] + aldd));
        }
#pragma unroll
        for (int off = 16; off; off >>= 1) m = fmaxf(m, __shfl_xor_sync(FULL, m, off));
        exs = __expf(m_self - m);
        accx = exs * hv0.x;
        accy = exs * hv0.y;
        den = 0.f;
        for (int base = 0; base < deg; base += 32) {
            int jl = base + lane;
            int s_l = 0; float ex_l = 0.f;
            if (jl < deg) {
                s_l = g_csrc[row + jl];
                ex_l = __expf(lrelu(g_als[s_l] + aldd) - m);
            }
            den += ex_l;
            int cnt = deg - base; if (cnt > 32) cnt = 32;
            int k = 0;
            for (; k + 4 <= cnt; k += 4) {
                int   s0 = __shfl_sync(FULL, s_l, k + 0);
                int   s1 = __shfl_sync(FULL, s_l, k + 1);
                int   s2 = __shfl_sync(FULL, s_l, k + 2);
                int   s3 = __shfl_sync(FULL, s_l, k + 3);
                float x0 = __shfl_sync(FULL, ex_l, k + 0);
                float x1 = __shfl_sync(FULL, ex_l, k + 1);
                float x2 = __shfl_sync(FULL, ex_l, k + 2);
                float x3 = __shfl_sync(FULL, ex_l, k + 3);
                float2 v0 = __half22float2(h[(size_t)s0 * 32 + lane]);
                float2 v1 = __half22float2(h[(size_t)s1 * 32 + lane]);
                float2 v2 = __half22float2(h[(size_t)s2 * 32 + lane]);
                float2 v3 = __half22float2(h[(size_t)s3 * 32 + lane]);
                accx = fmaf(x0, v0.x, accx); accy = fmaf(x0, v0.y, accy);
                accx = fmaf(x1, v1.x, accx); accy = fmaf(x1, v1.y, accy);
                accx = fmaf(x2, v2.x, accx); accy = fmaf(x2, v2.y, accy);
                accx = fmaf(x3, v3.x, accx); accy = fmaf(x3, v3.y, accy);
            }
            for (; k < cnt; k++) {
                float ex = __shfl_sync(FULL, ex_l, k);
                int   s  = __shfl_sync(FULL, s_l, k);
                float2 hv = __half22float2(h[(size_t)s * 32 + lane]);
                accx = fmaf(ex, hv.x, accx);
                accy = fmaf(ex, hv.y, accy);
            }
        }
    }
#pragma unroll
    for (int off = 16; off; off >>= 1) den += __shfl_xor_sync(FULL, den, off);
    den += exs;   // self-loop term (warp-uniform)
    float inv = 1.f / den;
    float2 o;
    o.x = elu_(accx * inv + bs[2 * lane + 0]);
    o.y = elu_(accy * inv + bs[2 * lane + 1]);
    *(float2*)(g_hx + (size_t)d * HH + 2 * lane) = o;
}

// ---------------- MLP head + pooled output, packed f32x2 FMA ----------------
__global__ __launch_bounds__(128) void final_kernel(
    const float* __restrict__ mw1, const float* __restrict__ mb1,
    const float* __restrict__ mw2, const float* __restrict__ mb2,
    const void* __restrict__ batch, float* __restrict__ out)
{
    __shared__ __align__(16) float mw1T[64 * 64];   // transposed: [j*64 + c]
    __shared__ __align__(16) float mw2s[64 * CC];
    __shared__ float mb1s[64], mb2s[CC];
    int tid = threadIdx.x;
    for (int i = tid; i < 64 * 64; i += 128) {
        int c = i >> 6, j = i & 63;
        mw1T[j * 64 + c] = mw1[i];
    }
    for (int i = tid; i < 64 * CC; i += 128) mw2s[i] = mw2[i];
    if (tid < 64) mb1s[tid] = mb1[tid];
    if (tid < CC) mb2s[tid] = mb2[tid];
    __syncthreads();

    int row = blockIdx.x * 128 + tid;
    int lane = tid & 31;
    bool active = row < NN;

    float o[CC];
#pragma unroll
    for (int c = 0; c < CC; c++) o[c] = 0.f;
    int g = 0;

    if (active) {
        size_t base = (size_t)row * HH;
        // load node features as 32 packed f32x2 pairs
        ull hf2[32];
        const ulonglong2* hp2 = (const ulonglong2*)(g_hx + base);
#pragma unroll
        for (int i = 0; i < 16; i++) {
            ulonglong2 p = hp2[i];
            hf2[2 * i + 0] = p.x;
            hf2[2 * i + 1] = p.y;
        }
        // out accumulators packed in pairs of classes
        ull oc2[CC / 2];
#pragma unroll
        for (int c2 = 0; c2 < CC / 2; c2++) oc2[c2] = pack2(mb2s[2 * c2], mb2s[2 * c2 + 1]);

        const ulonglong2* m1 = (const ulonglong2*)mw1T;
#pragma unroll 4
        for (int j = 0; j < 64; j++) {
            ull t2 = pack2(mb1s[j], 0.f);
#pragma unroll
            for (int c4 = 0; c4 < 16; c4++) {
                ulonglong2 w = m1[j * 16 + c4];
                t2 = fma2(hf2[2 * c4 + 0], w.x, t2);
                t2 = fma2(hf2[2 * c4 + 1], w.y, t2);
            }
            float tlo, thi;
            unpack2(t2, tlo, thi);
            float t = fmaxf(tlo + thi, 0.f);
            ull tt = pack2(t, t);
            const ull* w2 = (const ull*)(mw2s + j * CC);   // 10 floats = 5 pairs, 8B-aligned
#pragma unroll
            for (int c2 = 0; c2 < CC / 2; c2++) oc2[c2] = fma2(tt, w2[c2], oc2[c2]);
        }
#pragma unroll
        for (int c2 = 0; c2 < CC / 2; c2++) unpack2(oc2[c2], o[2 * c2], o[2 * c2 + 1]);

        if (g_i64) g = (int)((const long long*)batch)[row];
        else       g = ((const int*)batch)[row];
    }

    // batch is sorted -> most warps graph-uniform: in-warp reduce, 1 atomic/col/warp
    unsigned mask = 0xffffffffu;
    int g0 = __shfl_sync(mask, g, 0);
    bool uni = __all_sync(mask, g == g0);
    if (uni) {
#pragma unroll
        for (int c = 0; c < CC; c++) {
            float v = o[c];
#pragma unroll
            for (int off = 16; off > 0; off >>= 1) v += __shfl_xor_sync(mask, v, off);
            if (lane == 0) atomicAdd(&out[g0 * CC + c], v);
        }
    } else {
        if (active) {
#pragma unroll
            for (int c = 0; c < CC; c++) atomicAdd(&out[g * CC + c], o[c]);
        }
    }
}

// ---------------- launch (single stream, 10 launches) ----------------
extern "C" void kernel_launch(void* const* d_in, const int* in_sizes, int n_in,
                              void* d_out, int out_size) {
    const float* x     = (const float*)d_in[0];
    const int*   ei_w  = (const int*)d_in[1];
    const void*  batch = d_in[2];
    const float* W1  = (const float*)d_in[3];
    const float* as1 = (const float*)d_in[4];
    const float* ad1 = (const float*)d_in[5];
    const float* b1  = (const float*)d_in[6];
    const float* W2  = (const float*)d_in[7];
    const float* as2 = (const float*)d_in[8];
    const float* ad2 = (const float*)d_in[9];
    const float* b2  = (const float*)d_in[10];
    const float* mw1 = (const float*)d_in[11];
    const float* mb1 = (const float*)d_in[12];
    const float* mw2 = (const float*)d_in[13];
    const float* mb2 = (const float*)d_in[14];
    float* out = (float*)d_out;

    int gb = (NN + 127) / 128;
    int nb = (NN + 255) / 256;
    int eb = (EE + 255) / 256;
    int wb = ((NN * 32) + 255) / 256;

    zero_kernel<<<nb, 256>>>(ei_w, out);
    prep_kernel<<<eb, 256>>>(ei_w);
    scan1_kernel<<<NB1, 1024>>>();
    scan3_kernel<<<nb, 256>>>();
    fill_kernel<<<eb, 256>>>(ei_w);

    gemm_gat<<<gb, 128>>>(0, x, W1, as1, ad1);
    gather_kernel<<<wb, 256>>>(b1);

    gemm_gat<<<gb, 128>>>(1, x, W2, as2, ad2);
    gather_kernel<<<wb, 256>>>(b2);

    final_kernel<<<gb, 128>>>(mw1, mb1, mw2, mb2, batch, out);
}